// round 6
// baseline (speedup 1.0000x reference)
#include <cuda_runtime.h>
#include <cstdint>

// YoloLayer2: x (16, 3*85, 76, 76) f32 -> out (16, 3, 76, 76, 85) f32
// Per (b,a): transpose [85 x 5776] -> [5776 x 85] with elementwise transforms.
// TILE_P = 76 = one image row per tile: exact tiling, hj == blockIdx.x.

#define NUM_B 16
#define NUM_A 3
#define DIM_W 76
#define HW (DIM_W * DIM_W)        // 5776
#define ATTR 85
#define TILE_P 76                 // one row of pixels (exact: 76 tiles per ba)
#define V4 (TILE_P / 4)           // 19 float4 per attr row
#define NTHREADS 256
#define ITEMS (ATTR * V4)         // 1615 float4 work items per tile

// sigmoid(v) = 0.5*tanh(v/2) + 0.5  -- single MUFU (tanh.approx) + FMA
__device__ __forceinline__ float fsigmoid(float v) {
    float t;
    asm("tanh.approx.f32 %0, %1;" : "=f"(t) : "f"(v * 0.5f));
    return fmaf(t, 0.5f, 0.5f);
}

__device__ __forceinline__ float4 ldcs4(const float* p) {
    float4 r;
    asm("ld.global.cs.v4.f32 {%0,%1,%2,%3}, [%4];"
        : "=f"(r.x), "=f"(r.y), "=f"(r.z), "=f"(r.w) : "l"(p));
    return r;
}

__device__ __forceinline__ void stcs4(float* p, float4 v) {
    asm volatile("st.global.cs.v4.f32 [%0], {%1,%2,%3,%4};"
                 :: "l"(p), "f"(v.x), "f"(v.y), "f"(v.z), "f"(v.w) : "memory");
}

__global__ __launch_bounds__(NTHREADS)
void yolo_kernel(const float* __restrict__ x, float* __restrict__ out) {
    __shared__ float sm[TILE_P * ATTR];   // 25840 bytes

    const int hj = blockIdx.x;            // image row == tile index (exact)
    const int ba = blockIdx.y;            // b*3 + a, 0..47
    const int a  = ba % NUM_A;

    // anchor_w = masked[0:3] = {10,13,16}; anchor_h = masked[1:4] = {13,16,30}
    const float AW[3] = {10.0f, 13.0f, 16.0f};
    const float AH[3] = {13.0f, 16.0f, 30.0f};
    const float sw = AW[a] * (1.0f / 608.0f);
    const float sh = AH[a] * (1.0f / 608.0f);
    const float fh = (float)hj;
    const int   p0 = hj * TILE_P;
    const int  tid = threadIdx.x;

    const float* __restrict__ base_in = x + (size_t)ba * ATTR * HW + p0;

    // Element-parallel: ITEMS = 1615 float4 items over 256 threads.
    // attr = idx/19, pl = (idx%19)*4. No boundary predication: exact tiling.
    for (int idx = tid; idx < ITEMS; idx += NTHREADS) {
        const int attr = idx / V4;
        const int pl   = (idx - attr * V4) << 2;

        float4 v = ldcs4(base_in + attr * HW + pl);
        float vv[4] = {v.x, v.y, v.z, v.w};
        float r[4];

        if (attr >= 4) {
            #pragma unroll
            for (int k = 0; k < 4; k++) r[k] = fsigmoid(vv[k]);
        } else if (attr == 0) {
            #pragma unroll
            for (int k = 0; k < 4; k++)
                r[k] = ((float)(pl + k) + fsigmoid(vv[k])) * (1.0f / 76.0f);
        } else if (attr == 1) {
            #pragma unroll
            for (int k = 0; k < 4; k++)
                r[k] = (fh + fsigmoid(vv[k])) * (1.0f / 76.0f);
        } else if (attr == 2) {
            #pragma unroll
            for (int k = 0; k < 4; k++) r[k] = __expf(vv[k]) * sw;
        } else { // attr == 3
            #pragma unroll
            for (int k = 0; k < 4; k++) r[k] = __expf(vv[k]) * sh;
        }

        // Transposed smem store: stride 85 floats between pixels
        float* __restrict__ row = sm + pl * ATTR + attr;
        #pragma unroll
        for (int k = 0; k < 4; k++) row[k * ATTR] = r[k];
    }
    __syncthreads();

    // Coalesced streaming write: 76*85 = 6460 floats = 1615 float4 (exact).
    float* __restrict__ base_out = out + (size_t)(ba * HW + p0) * ATTR;
    const float4* __restrict__ s4 = (const float4*)sm;
    for (int k = tid; k < ITEMS; k += NTHREADS) {
        stcs4((float*)base_out + (k << 2), s4[k]);
    }
}

extern "C" void kernel_launch(void* const* d_in, const int* in_sizes, int n_in,
                              void* d_out, int out_size) {
    const float* x = (const float*)d_in[0];
    float* out = (float*)d_out;
    dim3 grid(TILE_P, NUM_B * NUM_A);   // (76, 48) = 3648 blocks
    yolo_kernel<<<grid, NTHREADS>>>(x, out);
}

// round 7
// speedup vs baseline: 1.1476x; 1.1476x over previous
#include <cuda_runtime.h>

// YoloLayer2: x (16, 3*85, 76, 76) f32 -> out (16, 3, 76, 76, 85) f32
// R2 structure (best measured) + evict-first loads, default (cached) stores.

#define NUM_B 16
#define NUM_A 3
#define DIM_H 76
#define DIM_W 76
#define HW (DIM_H * DIM_W)        // 5776
#define ATTR 85
#define TILE_P 64                 // pixels per block (smem = 64*85*4 = 21760 B)
#define V4 (TILE_P / 4)           // 16 float4 per attr row
#define NTHREADS 256

// sigmoid(v) = 0.5*tanh(v/2) + 0.5  -- single MUFU (tanh.approx) + FMA
__device__ __forceinline__ float fsigmoid(float v) {
    float t;
    asm("tanh.approx.f32 %0, %1;" : "=f"(t) : "f"(v * 0.5f));
    return fmaf(t, 0.5f, 0.5f);
}

// streaming load: input data is dead after one read -> evict-first keeps L2
// capacity for the (cache-beneficial) write stream
__device__ __forceinline__ float4 ldcs4(const float* p) {
    float4 r;
    asm("ld.global.cs.v4.f32 {%0,%1,%2,%3}, [%4];"
        : "=f"(r.x), "=f"(r.y), "=f"(r.z), "=f"(r.w) : "l"(p));
    return r;
}

__global__ __launch_bounds__(NTHREADS)
void yolo_kernel(const float* __restrict__ x, float* __restrict__ out) {
    __shared__ float sm[TILE_P * ATTR];   // 21760 bytes

    const int tile = blockIdx.x;          // pixel tile within (b,a)
    const int ba   = blockIdx.y;          // b*3 + a, 0..47
    const int a    = ba % NUM_A;

    // anchor_w = masked[0:3] = {10,13,16}; anchor_h = masked[1:4] = {13,16,30}
    const float AW[3] = {10.0f, 13.0f, 16.0f};
    const float AH[3] = {13.0f, 16.0f, 30.0f};
    const float sw = AW[a] * (1.0f / 608.0f);
    const float sh = AH[a] * (1.0f / 608.0f);

    const int p0     = tile * TILE_P;
    const int nvalid = min(TILE_P, HW - p0);   // 64, or 16 on the last tile
    const int tid    = threadIdx.x;

    const float* __restrict__ base_in = x + (size_t)ba * ATTR * HW + p0;

    // Element-parallel compute: ATTR * V4 = 1360 float4 elements across 256
    // threads. Loads are independent (high MLP) and coalesced per attr row.
    for (int idx = tid; idx < ATTR * V4; idx += NTHREADS) {
        const int attr = idx >> 4;        // idx / 16
        const int pl   = (idx & 15) << 2; // local pixel (multiple of 4)
        if (pl >= nvalid) continue;

        float4 v = ldcs4(base_in + attr * HW + pl);
        float vv[4] = {v.x, v.y, v.z, v.w};
        float r[4];

        if (attr >= 4) {
            #pragma unroll
            for (int k = 0; k < 4; k++) r[k] = fsigmoid(vv[k]);
        } else if (attr == 0) {
            #pragma unroll
            for (int k = 0; k < 4; k++) {
                const int p  = p0 + pl + k;
                const int wi = p % DIM_W;
                r[k] = ((float)wi + fsigmoid(vv[k])) * (1.0f / 76.0f);
            }
        } else if (attr == 1) {
            #pragma unroll
            for (int k = 0; k < 4; k++) {
                const int p  = p0 + pl + k;
                const int hj = p / DIM_W;
                r[k] = ((float)hj + fsigmoid(vv[k])) * (1.0f / 76.0f);
            }
        } else if (attr == 2) {
            #pragma unroll
            for (int k = 0; k < 4; k++) r[k] = __expf(vv[k]) * sw;
        } else { // attr == 3
            #pragma unroll
            for (int k = 0; k < 4; k++) r[k] = __expf(vv[k]) * sh;
        }

        // Transposed smem store: stride 85 between pixels
        float* __restrict__ row = sm + pl * ATTR + attr;
        #pragma unroll
        for (int k = 0; k < 4; k++) row[k * ATTR] = r[k];
    }
    __syncthreads();

    // Coalesced flat write of nvalid*85 contiguous floats (multiple of 4).
    // Default cache policy: dirty lines lingering in L2 reduce DRAM traffic.
    float* __restrict__ base_out = out + (size_t)(ba * HW + p0) * ATTR;
    const int total4 = (nvalid * ATTR) >> 2;
    const float4* __restrict__ s4 = (const float4*)sm;
    float4* __restrict__ o4 = (float4*)base_out;
    for (int k = tid; k < total4; k += NTHREADS) {
        o4[k] = s4[k];
    }
}

extern "C" void kernel_launch(void* const* d_in, const int* in_sizes, int n_in,
                              void* d_out, int out_size) {
    const float* x = (const float*)d_in[0];
    float* out = (float*)d_out;
    dim3 grid((HW + TILE_P - 1) / TILE_P, NUM_B * NUM_A);  // (91, 48)
    yolo_kernel<<<grid, NTHREADS>>>(x, out);
}